// round 9
// baseline (speedup 1.0000x reference)
#include <cuda_runtime.h>

#define B_  2
#define N_  30000
#define C_  32
#define H_  96
#define W_  96
#define D_  96
#define K_  27
#define V_  8
#define TPB 256
#define CS_ (H_*W_*D_)
#define BS_ (C_*CS_)
#define IK_ (C_*K_)        /* 864 */
#define NT_ (V_*K_)        /* 216 */
#define MT  120            /* pass-2 vertices per CTA */
#define KC  32             /* pass-2 ik chunk */

struct alignas(16) S8 { short s[8]; };

__device__ float2 g_wP[(IK_/2) * C_];                         // packed weight pairs
__device__ __align__(128) float g_vox2[(size_t)B_ * CS_ * C_];   // channel-last voxels
__device__ __align__(128) float g_feat[(size_t)B_ * N_ * IK_];   // fp32 feats, 207MB

__device__ __forceinline__ void ffma2(unsigned long long& acc,
                                      unsigned long long a,
                                      unsigned long long b)
{
    asm("fma.rn.f32x2 %0, %1, %2, %0;" : "+l"(acc) : "l"(a), "l"(b));
}

__global__ void wt_pack_kernel(const float* __restrict__ w)
{
    int idx = blockIdx.x * blockDim.x + threadIdx.x;
    if (idx < (IK_ / 2) * C_) {
        int o  = idx % C_;
        int tp = idx / C_;
        int rt0 = 2 * tp, rt1 = 2 * tp + 1;            // rt = k*32 + i
        int k0 = rt0 / C_, i0 = rt0 % C_;
        int k1 = rt1 / C_, i1 = rt1 % C_;
        g_wP[idx] = make_float2(w[(o * C_ + i0) * K_ + k0],
                                w[(o * C_ + i1) * K_ + k1]);
    }
}

/* (B,C,P) -> (B,P,C): 32c x 64p tiles, LDG.128 / STG.128 */
__global__ __launch_bounds__(256)
void vox_transpose_kernel(const float* __restrict__ vox)
{
    __shared__ float t[32][65];
    const int b    = blockIdx.y;
    const size_t p0 = (size_t)blockIdx.x * 64;
    const int tid = threadIdx.x;
    {
        const int pv = tid & 15, c0 = tid >> 4;
        const float* src = vox + (size_t)b * BS_ + p0 + 4 * pv;
        #pragma unroll
        for (int h = 0; h < 2; ++h) {
            const int c = c0 + 16 * h;
            const float4 r = *(const float4*)(src + (size_t)c * CS_);
            t[c][4*pv+0] = r.x; t[c][4*pv+1] = r.y;
            t[c][4*pv+2] = r.z; t[c][4*pv+3] = r.w;
        }
    }
    __syncthreads();
    {
        const int cv = tid & 7, p = tid >> 3;
        float* dst = g_vox2 + ((size_t)b * CS_ + p0) * C_ + 4 * cv;
        #pragma unroll
        for (int h = 0; h < 2; ++h) {
            const int pp = p + 32 * h;
            const float4 r = make_float4(t[4*cv+0][pp], t[4*cv+1][pp],
                                         t[4*cv+2][pp], t[4*cv+3][pp]);
            *(float4*)(dst + (size_t)pp * C_) = r;
        }
    }
}

/* ---------- Pass 1: sample + trilinear blend -> g_feat ---------- */
__global__ __launch_bounds__(TPB, 4)
void nfs_sample_kernel(const float* __restrict__ verts)
{
    __shared__ float s_win[2 * 64 * 32];       /* 2 windows        16384 B */
    __shared__ S8    s_cc[NT_];                /* corner slots      3456 B */
    __shared__ float s_cw[NT_ * 8];            /* corner weights    6912 B */
    __shared__ int   s_wb[V_ * 3];             /* window bases        96 B */

    const int tid  = threadIdx.x;
    const int w    = tid >> 5;
    const int lane = tid & 31;
    const int gv0  = blockIdx.x * V_;
    const int b    = gv0 / N_;

    // ---- Phase A: per-(vertex,sample) slot offsets + trilinear weights ----
    if (tid < NT_) {
        const int v = tid / K_, k = tid % K_;
        const int gv = gv0 + v;
        const float x = verts[gv * 3 + 0];
        const float y = verts[gv * 3 + 1];
        const float z = verts[gv * 3 + 2];

        const int p = k / 9 - 1;
        const int q = (k / 3) % 3 - 1;
        const int r = k % 3 - 1;
        const float sc = (float)(2.0 / (D_ - 1));

        float ix = (x + (float)p * sc + 1.0f) * 0.5f * (float)(D_ - 1);
        float iy = (y + (float)q * sc + 1.0f) * 0.5f * (float)(W_ - 1);
        float iz = (z + (float)r * sc + 1.0f) * 0.5f * (float)(H_ - 1);
        ix = fminf(fmaxf(ix, 0.0f), (float)(D_ - 1));
        iy = fminf(fmaxf(iy, 0.0f), (float)(W_ - 1));
        iz = fminf(fmaxf(iz, 0.0f), (float)(H_ - 1));
        const int x0 = (int)floorf(ix), y0 = (int)floorf(iy), z0 = (int)floorf(iz);
        const int x1 = min(x0 + 1, D_ - 1);
        const int y1 = min(y0 + 1, W_ - 1);
        const int z1 = min(z0 + 1, H_ - 1);
        const float fx = ix - (float)x0, fy = iy - (float)y0, fz = iz - (float)z0;
        const float gx = 1.0f - fx, gy = 1.0f - fy, gz = 1.0f - fz;

        float cxp = (x + 1.0f) * 0.5f * (float)(D_ - 1);
        float cyp = (y + 1.0f) * 0.5f * (float)(W_ - 1);
        float czp = (z + 1.0f) * 0.5f * (float)(H_ - 1);
        cxp = fminf(fmaxf(cxp, 0.0f), (float)(D_ - 1));
        cyp = fminf(fmaxf(cyp, 0.0f), (float)(W_ - 1));
        czp = fminf(fmaxf(czp, 0.0f), (float)(H_ - 1));
        const int wbx = (int)floorf(cxp) - 1;
        const int wby = (int)floorf(cyp) - 1;
        const int wbz = (int)floorf(czp) - 1;
        if (k == 0) {
            s_wb[v * 3 + 0] = wbx;
            s_wb[v * 3 + 1] = wby;
            s_wb[v * 3 + 2] = wbz;
        }

        const int sx0 = min(max(x0 - wbx, 0), 3),      sx1 = min(max(x1 - wbx, 0), 3);
        const int sy0 = min(max(y0 - wby, 0), 3) * 4,  sy1 = min(max(y1 - wby, 0), 3) * 4;
        const int sz0 = min(max(z0 - wbz, 0), 3) * 16, sz1 = min(max(z1 - wbz, 0), 3) * 16;

        short* cc = s_cc[tid].s;           // slot offsets premultiplied by 32
        float* cw = s_cw + tid * 8;
        cc[0] = (short)((sz0 + sy0 + sx0) * 32);  cw[0] = gz * gy * gx;
        cc[1] = (short)((sz0 + sy0 + sx1) * 32);  cw[1] = gz * gy * fx;
        cc[2] = (short)((sz0 + sy1 + sx0) * 32);  cw[2] = gz * fy * gx;
        cc[3] = (short)((sz0 + sy1 + sx1) * 32);  cw[3] = gz * fy * fx;
        cc[4] = (short)((sz1 + sy0 + sx0) * 32);  cw[4] = fz * gy * gx;
        cc[5] = (short)((sz1 + sy0 + sx1) * 32);  cw[5] = fz * gy * fx;
        cc[6] = (short)((sz1 + sy1 + sx0) * 32);  cw[6] = fz * fy * gx;
        cc[7] = (short)((sz1 + sy1 + sx1) * 32);  cw[7] = fz * fy * fx;
    }
    __syncthreads();

    // ---- Phase B: 4 phases x 2 vertices: vectorized gather, then blend->GMEM ----
    const float* vbase = g_vox2 + (size_t)b * CS_ * C_;
    float* fbase = g_feat + (size_t)gv0 * IK_;
    for (int h = 0; h < 4; ++h) {
        const int v    = 2 * h + (w >> 2);     // 4 warps per vertex
        const int jb   = (w & 3) * 16;         // 16 rows per warp
        const int r4   = lane >> 3;
        const int cq   = lane & 7;
        const int wbx  = s_wb[v * 3 + 0];
        const int wby  = s_wb[v * 3 + 1];
        const int wbz  = s_wb[v * 3 + 2];
        float* winv = s_win + (v & 1) * 2048;

        float4 tmp[4];
        #pragma unroll
        for (int it = 0; it < 4; ++it) {       // 4 LDG.128 per warp
            const int j  = jb + it * 4 + r4;
            const int cx = min(max(wbx + (j & 3), 0), D_ - 1);
            const int cy = min(max(wby + ((j >> 2) & 3), 0), W_ - 1);
            const int cz = min(max(wbz + (j >> 4), 0), H_ - 1);
            const int ro = (cz * W_ + cy) * D_ + cx;
            tmp[it] = *(const float4*)(vbase + (size_t)ro * C_ + cq * 4);
        }
        #pragma unroll
        for (int it = 0; it < 4; ++it) {       // 4 STS.128
            const int j = jb + it * 4 + r4;
            *(float4*)(winv + j * 32 + cq * 4) = tmp[it];
        }
        __syncthreads();

        // blend 2*27 = 54 tasks over 8 warps; lane = channel; store to GMEM
        for (int t = w; t < 2 * K_; t += 8) {
            const int vloc = t / K_, k = t % K_;
            const int vv = 2 * h + vloc;
            const int tg = vv * K_ + k;
            const S8 cc = s_cc[tg];
            const float4 wA = ((const float4*)s_cw)[tg * 2];
            const float4 wB = ((const float4*)s_cw)[tg * 2 + 1];
            const float* wv = s_win + vloc * 2048 + lane;
            float acc;
            acc  = wv[cc.s[0]] * wA.x;
            acc += wv[cc.s[1]] * wA.y;
            acc += wv[cc.s[2]] * wA.z;
            acc += wv[cc.s[3]] * wA.w;
            acc += wv[cc.s[4]] * wB.x;
            acc += wv[cc.s[5]] * wB.y;
            acc += wv[cc.s[6]] * wB.z;
            acc += wv[cc.s[7]] * wB.w;
            fbase[(size_t)vv * IK_ + k * C_ + lane] = acc;   // 128B/warp STG
        }
        __syncthreads();
    }
}

/* ---------- Pass 2: out = feat(60000x864) * wT(864x32) + bias ---------- */
__global__ __launch_bounds__(256, 4)
void nfs_gemm_kernel(const float* __restrict__ bias, float* __restrict__ out)
{
    __shared__ float s_tile[MT * KC];          // 15360 B
    const int tid  = threadIdx.x;
    const int w    = tid >> 5;
    const int lane = tid & 31;
    const int v0   = blockIdx.x * MT;

    unsigned long long acc[15];
    #pragma unroll
    for (int i = 0; i < 15; ++i) acc[i] = 0ull;

    for (int c = 0; c < IK_ / KC; ++c) {       // 27 chunks
        const int ik0 = c * KC;
        __syncthreads();                       // previous chunk fully consumed
        #pragma unroll 2
        for (int idx = tid; idx < MT * (KC / 4); idx += 256) {
            const int row = idx >> 3, seg = idx & 7;
            *(float4*)&s_tile[row * KC + seg * 4] =
                __ldg((const float4*)&g_feat[(size_t)(v0 + row) * IK_ + ik0 + seg * 4]);
        }
        __syncthreads();

        const int tp0 = ik0 >> 1;
        #pragma unroll
        for (int pp = 0; pp < 16; pp += 2) {
            const unsigned long long w01 =
                *(const unsigned long long*)&g_wP[(tp0 + pp) * C_ + lane];
            const unsigned long long w23 =
                *(const unsigned long long*)&g_wP[(tp0 + pp + 1) * C_ + lane];
            #pragma unroll
            for (int vi = 0; vi < 15; ++vi) {
                const ulonglong2 f =
                    *(const ulonglong2*)&s_tile[(w * 15 + vi) * KC + pp * 2];
                ffma2(acc[vi], f.x, w01);
                ffma2(acc[vi], f.y, w23);
            }
        }
    }

    const float bv = __ldg(bias + lane);
    #pragma unroll
    for (int vi = 0; vi < 15; ++vi) {
        float lo, hi;
        asm("mov.b64 {%0,%1}, %2;" : "=f"(lo), "=f"(hi) : "l"(acc[vi]));
        out[(size_t)(v0 + w * 15 + vi) * C_ + lane] = lo + hi + bv;
    }
}

extern "C" void kernel_launch(void* const* d_in, const int* in_sizes, int n_in,
                              void* d_out, int out_size)
{
    const float* vox   = (const float*)d_in[0];  // (2,32,96,96,96)
    const float* verts = (const float*)d_in[1];  // (2,30000,3)
    const float* cw    = (const float*)d_in[2];  // (32,32,1,27)
    const float* cb    = (const float*)d_in[3];  // (32,)
    float* out = (float*)d_out;                  // (2,30000,32)

    (void)in_sizes; (void)n_in; (void)out_size;

    vox_transpose_kernel<<<dim3(CS_ / 64, B_), 256>>>(vox);
    wt_pack_kernel<<<((IK_ / 2) * C_ + 255) / 256, 256>>>(cw);

    nfs_sample_kernel<<<(B_ * N_) / V_, TPB>>>(verts);      // 7500 blocks
    nfs_gemm_kernel<<<(B_ * N_) / MT, 256>>>(cb, out);      // 500 blocks
}